// round 14
// baseline (speedup 1.0000x reference)
#include <cuda_runtime.h>

#define NB 16
#define NS 4
#define NK 11
#define NBS (NB * NS)          // 64
#define NBSK (NB * NS * NK)    // 704
#define NTASK (2 * NBSK)       // 1408 half-map tasks
#define GRID 740               // 148 SMs x 5 CTAs: one full resident wave
#define NTHR 128

// Per-half-map partials + per-(b,s) arrival counters + work queue.
// Static device globals (no allocation). All counters are reset in-kernel
// so graph replays stay deterministic.
__device__ float    g_hsum[NTASK];
__device__ float    g_hmx [NTASK];
__device__ int      g_hmi [NTASK];
__device__ unsigned g_cnt [NBS];
__device__ unsigned g_task;
__device__ unsigned g_done;

// RELEASE-only atomic: orders prior .cg stores; no acquire half -> no
// CCTL.IVALL (L1 invalidate). Readers use ld.cg so no acquire needed.
__device__ __forceinline__ unsigned atom_add_release_gpu(unsigned* p, unsigned v)
{
    unsigned old;
    asm volatile("atom.release.gpu.global.add.u32 %0, [%1], %2;"
                 : "=r"(old) : "l"(p), "r"(v) : "memory");
    return old;
}

__global__ void __launch_bounds__(NTHR, 5)
keypoint_main_kernel(const float* __restrict__ cp,     // (16,4,22,128,128)
                     const float* __restrict__ heat,   // (16,11,128,128)
                     const float* __restrict__ lab,    // (16,11,11)
                     float* __restrict__ out)          // 128 floats
{
    const int t = threadIdx.x;           // 0..127
    __shared__ int   s_task;
    __shared__ int   s_fin;              // bs to finish, or -1
    __shared__ float ssum[4];
    __shared__ float smx[4];
    __shared__ int   smi[4];
    __shared__ float s_heat[NK];
    __shared__ float s_lab [NK];

    for (;;) {
        if (t == 0) s_task = (int)atomicAdd(&g_task, 1u);
        __syncthreads();
        const int task = s_task;
        if (task >= NTASK) break;

        const int half = task & 1;
        const int bsk  = task >> 1;      // 0..703
        const int k    = bsk % NK;
        const int bs   = bsk / NK;       // b*4+s
        const int b    = bs >> 2;

        const float4* __restrict__ hptr =
            (const float4*)(cp + ((size_t)(bs * 22 + k) << 14) + (half << 13));
        const float4* __restrict__ gptr =
            (const float4*)(heat + ((size_t)(b * NK + k) << 14) + (half << 13));

        float s0 = 0.0f, s1 = 0.0f;
        float mx = -__int_as_float(0x7f800000); // -inf
        int   mi = 0;

        // 2048 f4 per half-map / 128 thr = 16 f4 per thread per stream.
        // Batches of 4 (4 h + 4 g LDG.128 in flight) — R8's proven pattern.
        #pragma unroll
        for (int j = 0; j < 4; j++) {
            float4 h[4], g[4];
            #pragma unroll
            for (int u = 0; u < 4; u++) {
                const int v = t + (j * 4 + u) * NTHR;   // [0,2048)
                h[u] = hptr[v];
                g[u] = gptr[v];
            }
            #pragma unroll
            for (int u = 0; u < 4; u++) {
                const int v = t + (j * 4 + u) * NTHR;
                float d0 = h[u].x - g[u].x, d1 = h[u].y - g[u].y;
                float d2 = h[u].z - g[u].z, d3 = h[u].w - g[u].w;
                s0 = fmaf(d0, d0, s0);
                s1 = fmaf(d1, d1, s1);
                s0 = fmaf(d2, d2, s0);
                s1 = fmaf(d3, d3, s1);
                const int base = (half << 13) + (v << 2); // global elem index
                // ascending index -> strict > keeps first occurrence
                if (h[u].x > mx) { mx = h[u].x; mi = base; }
                if (h[u].y > mx) { mx = h[u].y; mi = base + 1; }
                if (h[u].z > mx) { mx = h[u].z; mi = base + 2; }
                if (h[u].w > mx) { mx = h[u].w; mi = base + 3; }
            }
        }
        float sum = s0 + s1;

        // Warp reduce (sum, argmax with lowest-index tiebreak)
        #pragma unroll
        for (int off = 16; off > 0; off >>= 1) {
            float osum = __shfl_down_sync(0xffffffffu, sum, off);
            float omx  = __shfl_down_sync(0xffffffffu, mx,  off);
            int   omi  = __shfl_down_sync(0xffffffffu, mi,  off);
            sum += osum;
            if (omx > mx || (omx == mx && omi < mi)) { mx = omx; mi = omi; }
        }
        const int w = t >> 5, l = t & 31;
        if (l == 0) { ssum[w] = sum; smx[w] = mx; smi[w] = mi; }
        __syncthreads();

        if (t == 0) {
            #pragma unroll
            for (int w2 = 1; w2 < 4; w2++) {
                sum += ssum[w2];
                if (smx[w2] > mx || (smx[w2] == mx && smi[w2] < mi)) {
                    mx = smx[w2]; mi = smi[w2];
                }
            }
            // publish half-map partials (L1-bypass -> L2)
            __stcg(&g_hsum[task], sum);
            __stcg(&g_hmx [task], mx);
            __stcg(&g_hmi [task], mi);

            // release orders the .cg stores before the count is visible
            const unsigned prev = atom_add_release_gpu(&g_cnt[bs], 1u);
            s_fin = (prev == 2 * NK - 1) ? bs : -1;
            if (s_fin >= 0) g_cnt[bs] = 0;    // reset for next replay
        }
        __syncthreads();

        const int fbs = s_fin;
        if (fbs >= 0) {
            // Parallel finisher: 11 threads, one per keypoint.
            if (t < NK) {
                const int k2  = t;
                const int fb  = fbs >> 2;
                const int tk0 = (fbs * NK + k2) * 2;     // half 0 task id
                float hs = __ldcg(&g_hsum[tk0]) + __ldcg(&g_hsum[tk0 + 1]);
                float m0 = __ldcg(&g_hmx[tk0]);
                int   i0 = __ldcg(&g_hmi[tk0]);
                const float m1 = __ldcg(&g_hmx[tk0 + 1]);
                const int   i1 = __ldcg(&g_hmi[tk0 + 1]);
                // half0 first; strict > keeps lower-index half on ties
                if (m1 > m0 || (m1 == m0 && i1 < i0)) { m0 = m1; i0 = i1; }

                const float* __restrict__ lp =
                    cp + ((size_t)(fbs * 22 + NK + k2) << 14);
                const float* __restrict__ lb = lab + (size_t)(fb * NK + k2) * 11;

                const float gx = lb[9];
                const float gy = lb[10];
                const bool valid = (gx > 0.0f) && (gy > 0.0f) &&
                                   (gx < 128.0f) && (gy < 128.0f);

                const float xf = (float)(i0 >> 7);    // index // 128
                const float yf = (float)(i0 & 127);   // index % 128

                const float dx = gx + lb[7] - xf - lp[7];
                const float dy = gy + lb[8] - yf - lp[8];
                const float xy_loss = dx * dx + dy * dy;

                const float c = 1.0f - m0;
                const float conf_loss = c * c;

                float cls = 0.0f;
                #pragma unroll
                for (int j = 0; j < 7; j++) {
                    const float d = lp[j] - lb[j];
                    cls = fmaf(d, d, cls);
                }

                s_heat[k2] = hs;
                s_lab [k2] = valid ? (cls + xy_loss + conf_loss) : 0.0f;
            }
            __syncthreads();
            if (t == 0) {
                float hsum = 0.0f, lsum = 0.0f;
                #pragma unroll
                for (int k2 = 0; k2 < NK; k2++) {
                    hsum += s_heat[k2];
                    lsum += s_lab [k2];
                }
                out[fbs]      = hsum;   // heat_loss (16,4)
                out[64 + fbs] = lsum;   // label_loss (16,4)
            }
        }
        __syncthreads();   // protect s_task / smem reuse next iteration
    }

    // Queue teardown: last CTA out resets the counters for the next replay.
    if (t == 0) {
        const unsigned d = atomicAdd(&g_done, 1u);
        if (d == GRID - 1) {
            g_task = 0;
            g_done = 0;
        }
    }
}

extern "C" void kernel_launch(void* const* d_in, const int* in_sizes, int n_in,
                              void* d_out, int out_size)
{
    const float* cp   = (const float*)d_in[0]; // combined_preds
    const float* heat = (const float*)d_in[1]; // heatmaps
    const float* lab  = (const float*)d_in[2]; // labels
    float* out = (float*)d_out;

    keypoint_main_kernel<<<GRID, NTHR>>>(cp, heat, lab, out);
}

// round 16
// speedup vs baseline: 1.1348x; 1.1348x over previous
#include <cuda_runtime.h>

#define NB 16
#define NS 4
#define NK 11
#define NBS (NB * NS)         // 64
#define NBSK (NB * NS * NK)   // 704
#define NTHR 128

// Scratch: per-(b,s,k) partials + per-(b,s) arrival counters. Static device
// globals (no allocation). Counters zero at load; finisher resets them each
// launch so graph replays stay deterministic.
__device__ float    g_part[2 * NBSK];
__device__ unsigned g_cnt[NBS];

// RELEASE-only atomic: orders prior .cg stores; no acquire half -> no
// CCTL.IVALL (L1 invalidate). Reader uses ld.cg so no acquire needed.
__device__ __forceinline__ unsigned atom_add_release_gpu(unsigned* p, unsigned v)
{
    unsigned old;
    asm volatile("atom.release.gpu.global.add.u32 %0, [%1], %2;"
                 : "=r"(old) : "l"(p), "r"(v) : "memory");
    return old;
}

// 128 threads, >=5 CTAs/SM resident: all 704 CTAs in ONE wave (148*5=740).
// Hot loop: 8 LDG.128 in flight per thread; argmax via FMNMX batch-max +
// (mx, batch-id) select-latch only — no per-element predicated chains.
__global__ void __launch_bounds__(NTHR, 5)
keypoint_main_kernel(const float* __restrict__ cp,     // (16,4,22,128,128)
                     const float* __restrict__ heat,   // (16,11,128,128)
                     const float* __restrict__ lab,    // (16,11,11)
                     float* __restrict__ out)          // 128 floats
{
    const int bsk = blockIdx.x;          // 0..703
    const int k   = bsk % NK;
    const int bs  = bsk / NK;            // b*4+s
    const int b   = bs >> 2;

    const float4* __restrict__ hptr =
        (const float4*)(cp + ((size_t)(bs * 22 + k) << 14));
    const float4* __restrict__ gptr =
        (const float4*)(heat + ((size_t)(b * NK + k) << 14));

    const int t = threadIdx.x;           // 0..127

    float s0 = 0.0f, s1 = 0.0f, s2 = 0.0f, s3 = 0.0f;
    float mx   = -__int_as_float(0x7f800000); // -inf
    int   bwin = 0;                           // winning batch id

    // 4096 f4/map / 128 thr = 32 f4 per thread per stream; 8 batches of 4.
    #pragma unroll
    for (int j = 0; j < 8; j++) {
        float4 h[4], g[4];
        #pragma unroll
        for (int u = 0; u < 4; u++) {
            const int v = t + (j * 4 + u) * NTHR;   // [0,4096)
            h[u] = hptr[v];
            g[u] = gptr[v];
        }
        float bm = -__int_as_float(0x7f800000);
        #pragma unroll
        for (int u = 0; u < 4; u++) {
            float d0 = h[u].x - g[u].x, d1 = h[u].y - g[u].y;
            float d2 = h[u].z - g[u].z, d3 = h[u].w - g[u].w;
            s0 = fmaf(d0, d0, s0);
            s1 = fmaf(d1, d1, s1);
            s2 = fmaf(d2, d2, s2);
            s3 = fmaf(d3, d3, s3);
            // FMNMX tree — no predicates in the hot loop
            bm = fmaxf(bm, fmaxf(fmaxf(h[u].x, h[u].y),
                                 fmaxf(h[u].z, h[u].w)));
        }
        // strict > keeps the earliest batch on ties (first occurrence)
        const bool take = (bm > mx);
        mx   = take ? bm : mx;
        bwin = take ? j  : bwin;
    }
    float sum = (s0 + s1) + (s2 + s3);

    // Cold path: reload the winning batch (4 LDG.128/thread, L2-hit) and
    // find the first element equal to mx (ascending -> first occurrence).
    int mi = 0x7fffffff;
    #pragma unroll
    for (int u = 0; u < 4; u++) {
        const int v = t + (bwin * 4 + u) * NTHR;
        const float4 h = hptr[v];
        const int base = v << 2;
        if (mi == 0x7fffffff && h.x == mx) mi = base;
        if (mi == 0x7fffffff && h.y == mx) mi = base + 1;
        if (mi == 0x7fffffff && h.z == mx) mi = base + 2;
        if (mi == 0x7fffffff && h.w == mx) mi = base + 3;
    }

    // Warp reduce (sum, argmax with lowest-index tiebreak)
    #pragma unroll
    for (int off = 16; off > 0; off >>= 1) {
        float osum = __shfl_down_sync(0xffffffffu, sum, off);
        float omx  = __shfl_down_sync(0xffffffffu, mx,  off);
        int   omi  = __shfl_down_sync(0xffffffffu, mi,  off);
        sum += osum;
        if (omx > mx || (omx == mx && omi < mi)) { mx = omx; mi = omi; }
    }

    __shared__ float ssum[4];
    __shared__ float smx[4];
    __shared__ int   smi[4];
    const int w = t >> 5, l = t & 31;
    if (l == 0) { ssum[w] = sum; smx[w] = mx; smi[w] = mi; }
    __syncthreads();

    if (t == 0) {
        #pragma unroll
        for (int w2 = 1; w2 < 4; w2++) {
            sum += ssum[w2];
            if (smx[w2] > mx || (smx[w2] == mx && smi[w2] < mi)) {
                mx = smx[w2]; mi = smi[w2];
            }
        }

        // ---- label-loss term for this (b,s,k) ----
        const float* __restrict__ lp =
            cp + ((size_t)(bs * 22 + NK + k) << 14);     // lb map, first 9 used
        const float* __restrict__ lb = lab + (size_t)(b * NK + k) * 11;

        const float gx = lb[9];
        const float gy = lb[10];
        const bool valid = (gx > 0.0f) && (gy > 0.0f) &&
                           (gx < 128.0f) && (gy < 128.0f);

        const float xf = (float)(mi >> 7);    // index // 128
        const float yf = (float)(mi & 127);   // index % 128

        const float dx = gx + lb[7] - xf - lp[7];
        const float dy = gy + lb[8] - yf - lp[8];
        const float xy_loss = dx * dx + dy * dy;

        const float c = 1.0f - mx;
        const float conf_loss = c * c;

        float cls = 0.0f;
        #pragma unroll
        for (int j = 0; j < 7; j++) {
            const float d = lp[j] - lb[j];
            cls = fmaf(d, d, cls);
        }

        // L1-bypass stores: land in L2, visible to any finisher on any SM.
        __stcg(&g_part[bsk], sum);
        __stcg(&g_part[NBSK + bsk],
               valid ? (cls + xy_loss + conf_loss) : 0.0f);

        // Release-only ordering; reader uses ld.cg (L1-bypass).
        const unsigned prev = atom_add_release_gpu(&g_cnt[bs], 1u);
        if (prev == NK - 1) {
            g_cnt[bs] = 0;               // reset for next graph replay
            float hsum = 0.0f, lsum = 0.0f;
            #pragma unroll
            for (int kk = 0; kk < NK; kk++) {
                hsum += __ldcg(&g_part[bs * NK + kk]);
                lsum += __ldcg(&g_part[NBSK + bs * NK + kk]);
            }
            out[bs]      = hsum;         // heat_loss (16,4)
            out[64 + bs] = lsum;         // label_loss (16,4)
        }
    }
}

extern "C" void kernel_launch(void* const* d_in, const int* in_sizes, int n_in,
                              void* d_out, int out_size)
{
    const float* cp   = (const float*)d_in[0]; // combined_preds
    const float* heat = (const float*)d_in[1]; // heatmaps
    const float* lab  = (const float*)d_in[2]; // labels
    float* out = (float*)d_out;

    keypoint_main_kernel<<<NBSK, NTHR>>>(cp, heat, lab, out);
}